// round 12
// baseline (speedup 1.0000x reference)
#include <cuda_runtime.h>
#include <cuda_bf16.h>
#include <cuda_fp16.h>
#include <cstdint>

// Problem constants
#define PB  16
#define PTV 128
#define PTH 64
#define PF  512
#define PH  512
#define PD  256
#define KDIM 512

#define MTILES 48
#define KITERS 32

// ---------------------------------------------------------------------------
// Device scratch
// ---------------------------------------------------------------------------
__device__ uint4 g_Afrag[MTILES * KITERS * 4 * 2 * 32];
__device__ uint4 g_Bfrag[2 * KITERS * 32 * 32];

__device__ float g_WvT[PB * PD * PTV];   // [b][d][t]
__device__ float g_Uhb[PB * PTH * PD];   // [b][s][d]

__device__ __forceinline__ uint32_t smem_u32(const void* p) {
    uint32_t a;
    asm("{ .reg .u64 t; cvta.to.shared.u64 t, %1; cvt.u32.u64 %0, t; }" : "=r"(a) : "l"(p));
    return a;
}
__device__ __forceinline__ void cp_async16(uint32_t smem_addr, const void* gptr) {
    asm volatile("cp.async.cg.shared.global [%0], [%1], 16;" :: "r"(smem_addr), "l"(gptr));
}
#define CP_COMMIT() asm volatile("cp.async.commit_group;" ::: "memory")
#define CP_WAIT(N)  asm volatile("cp.async.wait_group %0;" :: "n"(N) : "memory")

// Split-pair: packed bf16-hi of (a,b) [lo=a]; lop gets residual pair.
__device__ __forceinline__ uint32_t splitpair(float a, float b, uint32_t& lop) {
    uint32_t hp;
    asm("cvt.rn.bf16x2.f32 %0, %1, %2;" : "=r"(hp) : "f"(b), "f"(a));
    float ha = __uint_as_float(hp << 16);
    float hb = __uint_as_float(hp & 0xFFFF0000u);
    float la = a - ha;
    float lb = b - hb;
    asm("cvt.rn.bf16x2.f32 %0, %1, %2;" : "=r"(lop) : "f"(lb), "f"(la));
    return hp;
}

__device__ __forceinline__ void mma_bf16(float* c, uint32_t a0, uint32_t a1, uint32_t a2, uint32_t a3,
                                         uint32_t b0, uint32_t b1) {
    asm volatile(
        "mma.sync.aligned.m16n8k16.row.col.f32.bf16.bf16.f32 "
        "{%0,%1,%2,%3}, {%4,%5,%6,%7}, {%8,%9}, {%0,%1,%2,%3};"
        : "+f"(c[0]), "+f"(c[1]), "+f"(c[2]), "+f"(c[3])
        : "r"(a0), "r"(a1), "r"(a2), "r"(a3), "r"(b0), "r"(b1));
}

// Pack 2 f32 -> f16x2 (lo = x0), tanh both halves, return packed f16x2.
__device__ __forceinline__ uint32_t tanh2_f16(float x0, float x1) {
    uint32_t p, r;
    asm("cvt.rn.f16x2.f32 %0, %1, %2;" : "=r"(p) : "f"(x1), "f"(x0));
    asm("tanh.approx.f16x2 %0, %1;" : "=r"(r) : "r"(p));
    return r;
}

// ---------------------------------------------------------------------------
// Prep kernel. Blocks 0..767: A fragments (as before).
// Blocks 768..831: B fragments via coalesced smem staging (1 CTA per (mat,kit)).
// ---------------------------------------------------------------------------
__global__ __launch_bounds__(256) void prep_kernel(
    const float* __restrict__ v, const float* __restrict__ h,
    const float* __restrict__ W, const float* __restrict__ U)
{
    const int tid = threadIdx.x;
    if (blockIdx.x < 768) {
        int gid = blockIdx.x * 256 + tid;
        int lane = gid & 31;
        int mf   = (gid >> 5) & 3;
        int kit  = (gid >> 7) & 31;
        int tile = gid >> 12;

        int rloc = tile * 64 + mf * 16 + (lane >> 2);
        const float* r0p;
        if (tile < 32) r0p = v + (size_t)rloc * KDIM;
        else           r0p = h + (size_t)(rloc - 2048) * KDIM;
        const float* r1p = r0p + 8 * KDIM;
        int k0 = kit * 16 + (lane & 3) * 2;

        float2 x00 = *reinterpret_cast<const float2*>(r0p + k0);
        float2 x10 = *reinterpret_cast<const float2*>(r1p + k0);
        float2 x08 = *reinterpret_cast<const float2*>(r0p + k0 + 8);
        float2 x18 = *reinterpret_cast<const float2*>(r1p + k0 + 8);

        uint4 vh, vl;
        vh.x = splitpair(x00.x, x00.y, vl.x);
        vh.y = splitpair(x10.x, x10.y, vl.y);
        vh.z = splitpair(x08.x, x08.y, vl.z);
        vh.w = splitpair(x18.x, x18.y, vl.w);

        size_t base = ((((size_t)tile * KITERS + kit) * 4 + mf) * 2) * 32 + lane;
        g_Afrag[base]      = vh;
        g_Afrag[base + 32] = vl;
    } else {
        __shared__ float sW[16][264];       // padded, 16B-aligned rows
        int bb = blockIdx.x - 768;          // 0..63
        int mat = bb >> 5;
        int kit = bb & 31;
        const float* Bsrc = mat ? U : W;
        int k0 = kit * 16;

        for (int i = tid; i < 1024; i += 256) {      // 16 rows x 64 float4
            int r  = i >> 6;
            int n4 = (i & 63) << 2;
            float4 val = *reinterpret_cast<const float4*>(Bsrc + (size_t)(k0 + r) * PD + n4);
            *reinterpret_cast<float4*>(&sW[r][n4]) = val;
        }
        __syncthreads();

        for (int it = tid; it < 1024; it += 256) {
            int lane = it & 31;
            int nf   = it >> 5;
            int n  = nf * 8 + (lane >> 2);
            int kl = (lane & 3) * 2;
            float xa = sW[kl][n];
            float xb = sW[kl + 1][n];
            float xc = sW[kl + 8][n];
            float xd = sW[kl + 9][n];
            uint4 out;
            out.x = splitpair(xa, xb, out.z);
            out.y = splitpair(xc, xd, out.w);
            g_Bfrag[(((size_t)mat * KITERS + kit) * 32 + nf) * 32 + lane] = out;
        }
    }
}

// ---------------------------------------------------------------------------
// bf16 split-float MMA GEMM (unchanged from round 11)
// ---------------------------------------------------------------------------
__global__ __launch_bounds__(256) void mma_gemm_kernel(const float* __restrict__ bias)
{
    __shared__ __align__(16) char s_raw[32768];
    uint4* sbuf = reinterpret_cast<uint4*>(s_raw);
    const uint32_t sbase = smem_u32(s_raw);

    const int tile  = blockIdx.x >> 2;
    const int ntile = blockIdx.x & 3;
    const int tid   = threadIdx.x;
    const int lane  = tid & 31;
    const int wid   = tid >> 5;
    const int wm    = wid >> 2;
    const int wn    = wid & 3;
    const bool is_v = tile < 32;

    float acc[2][2][4];
#pragma unroll
    for (int mf = 0; mf < 2; mf++)
#pragma unroll
        for (int nf = 0; nf < 2; nf++)
#pragma unroll
            for (int r = 0; r < 4; r++) acc[mf][nf][r] = 0.0f;

    const uint4* Asrc = g_Afrag + (size_t)tile * (KITERS * 256);
    const uint4* Bsrc = g_Bfrag + ((size_t)(is_v ? 0 : 1) * KITERS * 32 + ntile * 8) * 32;

#pragma unroll
    for (int s = 0; s < 3; s++) {
        cp_async16(sbase + (s * 512 + tid) * 16,       Asrc + (size_t)s * 256 + tid);
        cp_async16(sbase + (s * 512 + 256 + tid) * 16, Bsrc + (size_t)s * 1024 + tid);
        CP_COMMIT();
    }

    const int aoff0 = ((wm * 2 + 0) * 2) * 32 + lane;
    const int boff0 = 256 + (wn * 2) * 32 + lane;

#pragma unroll 4
    for (int kit = 0; kit < KITERS; kit++) {
        const int p = kit & 3;
        CP_WAIT(2);
        __syncthreads();
        if (kit + 3 < KITERS) {
            const int s = (kit + 3) & 3;
            cp_async16(sbase + (s * 512 + tid) * 16,       Asrc + (size_t)(kit + 3) * 256 + tid);
            cp_async16(sbase + (s * 512 + 256 + tid) * 16, Bsrc + (size_t)(kit + 3) * 1024 + tid);
        }
        CP_COMMIT();

        const uint4* buf = sbuf + p * 512;
        uint4 Ah[2], Al[2], Bf[2];
        Ah[0] = buf[aoff0];
        Al[0] = buf[aoff0 + 32];
        Ah[1] = buf[aoff0 + 64];
        Al[1] = buf[aoff0 + 96];
        Bf[0] = buf[boff0];
        Bf[1] = buf[boff0 + 32];
#pragma unroll
        for (int mf = 0; mf < 2; mf++) {
#pragma unroll
            for (int nf = 0; nf < 2; nf++) {
                mma_bf16(acc[mf][nf], Ah[mf].x, Ah[mf].y, Ah[mf].z, Ah[mf].w, Bf[nf].x, Bf[nf].y);
                mma_bf16(acc[mf][nf], Ah[mf].x, Ah[mf].y, Ah[mf].z, Ah[mf].w, Bf[nf].z, Bf[nf].w);
                mma_bf16(acc[mf][nf], Al[mf].x, Al[mf].y, Al[mf].z, Al[mf].w, Bf[nf].x, Bf[nf].y);
            }
        }
    }
    __syncthreads();

    const int g  = lane >> 2;
    const int tc = (lane & 3) * 2;

    if (is_v) {
        float (*st)[72] = reinterpret_cast<float (*)[72]>(s_raw);
#pragma unroll
        for (int mf = 0; mf < 2; mf++) {
#pragma unroll
            for (int nf = 0; nf < 2; nf++) {
                int ml = wm * 32 + mf * 16 + g;
                int nl = wn * 16 + nf * 8 + tc;
                st[nl][ml]         = acc[mf][nf][0];
                st[nl + 1][ml]     = acc[mf][nf][1];
                st[nl][ml + 8]     = acc[mf][nf][2];
                st[nl + 1][ml + 8] = acc[mf][nf][3];
            }
        }
        __syncthreads();
        const int b  = tile >> 1;
        const int t0 = (tile & 1) * 64;
        const int d0 = ntile * 64;
        for (int i = tid; i < 64 * 16; i += 256) {
            int d  = i >> 4;
            int m4 = (i & 15) << 2;
            float4 val = *reinterpret_cast<const float4*>(&st[d][m4]);
            *reinterpret_cast<float4*>(
                g_WvT + ((size_t)(b * PD + d0 + d) << 7) + t0 + m4) = val;
        }
    } else {
#pragma unroll
        for (int mf = 0; mf < 2; mf++) {
            int row = (tile - 32) * 64 + wm * 32 + mf * 16 + g;
#pragma unroll
            for (int nf = 0; nf < 2; nf++) {
                int col = ntile * 64 + wn * 16 + nf * 8 + tc;
                float b0 = __ldg(bias + col);
                float b1 = __ldg(bias + col + 1);
                float2 o0 = make_float2(acc[mf][nf][0] + b0, acc[mf][nf][1] + b1);
                float2 o1 = make_float2(acc[mf][nf][2] + b0, acc[mf][nf][3] + b1);
                *reinterpret_cast<float2*>(g_Uhb + (size_t)row * PD + col)       = o0;
                *reinterpret_cast<float2*>(g_Uhb + (size_t)(row + 8) * PD + col) = o1;
            }
        }
    }
}

// ---------------------------------------------------------------------------
// Fused scores + softmax + context. Grid (16,16) = 256 CTAs, 256 threads.
// Phase A: f16x2 tanh (2 elems/MUFU), float4 su/sw broadcast loads.
// Phase B: v streamed via 2-stage cp.async (unchanged).
// ---------------------------------------------------------------------------
__global__ __launch_bounds__(256) void attn_fused_kernel(
    const float* __restrict__ v, const float* __restrict__ wvec,
    float* __restrict__ u)
{
    const int b = blockIdx.y;
    const int s0 = blockIdx.x * 4;
    const int tid = threadIdx.x;
    const int t = tid & 127;
    const int dh = tid >> 7;

    __shared__ float su[4][PD];
    __shared__ float sw[PD];
    __shared__ float rmax[4][4];
    __shared__ float rsum[4][4];
    __shared__ float sbeta[4][PTV];
    __shared__ float spA[4][PTV];
    __shared__ __align__(16) char sraw[32768];

    const uint32_t sb_addr = smem_u32(sraw);

    if (tid < PD) sw[tid] = wvec[tid];
    for (int i = tid; i < 4 * PD; i += 256)
        su[i >> 8][i & 255] = g_Uhb[((size_t)(b * PTH + s0 + (i >> 8)) << 8) + (i & 255)];

    // ---- Phase A ----
    const float4* wsrc = reinterpret_cast<const float4*>(g_WvT + ((size_t)b << 15));
#pragma unroll
    for (int j = 0; j < 4; j++)
        cp_async16(sb_addr + (j * 256 + tid) * 16, wsrc + j * 256 + tid);
    CP_COMMIT();

    float a0 = 0.f, a1 = 0.f, a2 = 0.f, a3 = 0.f;
    for (int c = 0; c < 8; c++) {
        const int p = c & 1;
        CP_WAIT(0);
        __syncthreads();
        if (c + 1 < 8) {
            const float4* src = wsrc + (size_t)(c + 1) * 1024;
            uint32_t dst = sb_addr + (p ^ 1) * 16384;
#pragma unroll
            for (int j = 0; j < 4; j++)
                cp_async16(dst + (j * 256 + tid) * 16, src + j * 256 + tid);
        }
        CP_COMMIT();

        const float* wb = reinterpret_cast<const float*>(sraw + p * 16384); // [32][128]
        const int rbase = dh * 16;
        const int dbase = c * 32 + rbase;
#pragma unroll
        for (int j = 0; j < 16; j += 4) {
            float wv0 = wb[(rbase + j + 0) * 128 + t];
            float wv1 = wb[(rbase + j + 1) * 128 + t];
            float wv2 = wb[(rbase + j + 2) * 128 + t];
            float wv3 = wb[(rbase + j + 3) * 128 + t];
            float4 w4 = *reinterpret_cast<const float4*>(&sw[dbase + j]);
            float4 s0v = *reinterpret_cast<const float4*>(&su[0][dbase + j]);
            float4 s1v = *reinterpret_cast<const float4*>(&su[1][dbase + j]);
            float4 s2v = *reinterpret_cast<const float4*>(&su[2][dbase + j]);
            float4 s3v = *reinterpret_cast<const float4*>(&su[3][dbase + j]);

            {
                uint32_t tp0 = tanh2_f16(s0v.x + wv0, s0v.y + wv1);
                uint32_t tp1 = tanh2_f16(s0v.z + wv2, s0v.w + wv3);
                __half2 h0 = *reinterpret_cast<__half2*>(&tp0);
                __half2 h1 = *reinterpret_cast<__half2*>(&tp1);
                a0 = fmaf(w4.x, __low2float(h0), a0);
                a0 = fmaf(w4.y, __high2float(h0), a0);
                a0 = fmaf(w4.z, __low2float(h1), a0);
                a0 = fmaf(w4.w, __high2float(h1), a0);
            }
            {
                uint32_t tp0 = tanh2_f16(s1v.x + wv0, s1v.y + wv1);
                uint32_t tp1 = tanh2_f16(s1v.z + wv2, s1v.w + wv3);
                __half2 h0 = *reinterpret_cast<__half2*>(&tp0);
                __half2 h1 = *reinterpret_cast<__half2*>(&tp1);
                a1 = fmaf(w4.x, __low2float(h0), a1);
                a1 = fmaf(w4.y, __high2float(h0), a1);
                a1 = fmaf(w4.z, __low2float(h1), a1);
                a1 = fmaf(w4.w, __high2float(h1), a1);
            }
            {
                uint32_t tp0 = tanh2_f16(s2v.x + wv0, s2v.y + wv1);
                uint32_t tp1 = tanh2_f16(s2v.z + wv2, s2v.w + wv3);
                __half2 h0 = *reinterpret_cast<__half2*>(&tp0);
                __half2 h1 = *reinterpret_cast<__half2*>(&tp1);
                a2 = fmaf(w4.x, __low2float(h0), a2);
                a2 = fmaf(w4.y, __high2float(h0), a2);
                a2 = fmaf(w4.z, __low2float(h1), a2);
                a2 = fmaf(w4.w, __high2float(h1), a2);
            }
            {
                uint32_t tp0 = tanh2_f16(s3v.x + wv0, s3v.y + wv1);
                uint32_t tp1 = tanh2_f16(s3v.z + wv2, s3v.w + wv3);
                __half2 h0 = *reinterpret_cast<__half2*>(&tp0);
                __half2 h1 = *reinterpret_cast<__half2*>(&tp1);
                a3 = fmaf(w4.x, __low2float(h0), a3);
                a3 = fmaf(w4.y, __high2float(h0), a3);
                a3 = fmaf(w4.z, __low2float(h1), a3);
                a3 = fmaf(w4.w, __high2float(h1), a3);
            }
        }
    }
    __syncthreads();

    // combine d-halves
    if (dh == 1) {
        spA[0][t] = a0; spA[1][t] = a1; spA[2][t] = a2; spA[3][t] = a3;
    }
    __syncthreads();

    float e0, e1, e2, e3;
    const int lane = t & 31;
    const int wq = t >> 5;
    if (dh == 0) {
        a0 += spA[0][t]; a1 += spA[1][t]; a2 += spA[2][t]; a3 += spA[3][t];
        float m0 = a0, m1 = a1, m2 = a2, m3 = a3;
#pragma unroll
        for (int off = 16; off; off >>= 1) {
            m0 = fmaxf(m0, __shfl_xor_sync(0xffffffffu, m0, off));
            m1 = fmaxf(m1, __shfl_xor_sync(0xffffffffu, m1, off));
            m2 = fmaxf(m2, __shfl_xor_sync(0xffffffffu, m2, off));
            m3 = fmaxf(m3, __shfl_xor_sync(0xffffffffu, m3, off));
        }
        if (lane == 0) { rmax[0][wq] = m0; rmax[1][wq] = m1; rmax[2][wq] = m2; rmax[3][wq] = m3; }
    }
    __syncthreads();
    if (dh == 0) {
        float m0 = fmaxf(fmaxf(rmax[0][0], rmax[0][1]), fmaxf(rmax[0][2], rmax[0][3]));
        float m1 = fmaxf(fmaxf(rmax[1][0], rmax[1][1]), fmaxf(rmax[1][2], rmax[1][3]));
        float m2 = fmaxf(fmaxf(rmax[2][0], rmax[2][1]), fmaxf(rmax[2][2], rmax[2][3]));
        float m3 = fmaxf(fmaxf(rmax[3][0], rmax[3][1]), fmaxf(rmax[3][2], rmax[3][3]));
        e0 = __expf(a0 - m0); e1 = __expf(a1 - m1);
        e2 = __expf(a2 - m2); e3 = __expf(a3 - m3);
        float s0v = e0, s1v = e1, s2v = e2, s3v = e3;
#pragma unroll
        for (int off = 16; off; off >>= 1) {
            s0v += __shfl_xor_sync(0xffffffffu, s0v, off);
            s1v += __shfl_xor_sync(0xffffffffu, s1v, off);
            s2v += __shfl_xor_sync(0xffffffffu, s2v, off);
            s3v += __shfl_xor_sync(0xffffffffu, s3v, off);
        }
        if (lane == 0) { rsum[0][wq] = s0v; rsum[1][wq] = s1v; rsum[2][wq] = s2v; rsum[3][wq] = s3v; }
    }
    __syncthreads();
    if (dh == 0) {
        float i0 = 1.0f / ((rsum[0][0] + rsum[0][1]) + (rsum[0][2] + rsum[0][3]));
        float i1 = 1.0f / ((rsum[1][0] + rsum[1][1]) + (rsum[1][2] + rsum[1][3]));
        float i2 = 1.0f / ((rsum[2][0] + rsum[2][1]) + (rsum[2][2] + rsum[2][3]));
        float i3 = 1.0f / ((rsum[3][0] + rsum[3][1]) + (rsum[3][2] + rsum[3][3]));
        sbeta[0][t] = e0 * i0;
        sbeta[1][t] = e1 * i1;
        sbeta[2][t] = e2 * i2;
        sbeta[3][t] = e3 * i3;
    }
    __syncthreads();

    // ---- Phase B: context ----
    const int f4 = t;
    const int th = dh;

    const float4* vsrc = reinterpret_cast<const float4*>(v + (size_t)b * PTV * PF);
#pragma unroll
    for (int j = 0; j < 4; j++)
        cp_async16(sb_addr + (j * 256 + tid) * 16, vsrc + j * 256 + tid);
    CP_COMMIT();

    float4 o0 = make_float4(0.f, 0.f, 0.f, 0.f);
    float4 o1 = make_float4(0.f, 0.f, 0.f, 0.f);
    float4 o2 = make_float4(0.f, 0.f, 0.f, 0.f);
    float4 o3 = make_float4(0.f, 0.f, 0.f, 0.f);

    for (int ch = 0; ch < 16; ch++) {
        const int p = ch & 1;
        CP_WAIT(0);
        __syncthreads();
        if (ch + 1 < 16) {
            const float4* src = vsrc + (size_t)(ch + 1) * 1024;
            uint32_t dst = sb_addr + (p ^ 1) * 16384;
#pragma unroll
            for (int j = 0; j < 4; j++)
                cp_async16(dst + (j * 256 + tid) * 16, src + j * 256 + tid);
        }
        CP_COMMIT();

        const float4* vs = reinterpret_cast<const float4*>(sraw + p * 16384); // [8][128]
#pragma unroll
        for (int j = 0; j < 4; j++) {
            int tl = th * 4 + j;
            int tt = ch * 8 + tl;
            float4 vr = vs[tl * 128 + f4];
            float b0 = sbeta[0][tt];
            float b1 = sbeta[1][tt];
            float b2 = sbeta[2][tt];
            float b3 = sbeta[3][tt];
            o0.x += b0 * vr.x; o0.y += b0 * vr.y; o0.z += b0 * vr.z; o0.w += b0 * vr.w;
            o1.x += b1 * vr.x; o1.y += b1 * vr.y; o1.z += b1 * vr.z; o1.w += b1 * vr.w;
            o2.x += b2 * vr.x; o2.y += b2 * vr.y; o2.z += b2 * vr.z; o2.w += b2 * vr.w;
            o3.x += b3 * vr.x; o3.y += b3 * vr.y; o3.z += b3 * vr.z; o3.w += b3 * vr.w;
        }
    }
    __syncthreads();

    float4* spB = reinterpret_cast<float4*>(sraw);
    if (th == 1) {
        spB[0 * 128 + f4] = o0;
        spB[1 * 128 + f4] = o1;
        spB[2 * 128 + f4] = o2;
        spB[3 * 128 + f4] = o3;
    }
    __syncthreads();
    if (th == 0) {
        float4 p0 = spB[0 * 128 + f4];
        float4 p1 = spB[1 * 128 + f4];
        float4 p2 = spB[2 * 128 + f4];
        float4 p3 = spB[3 * 128 + f4];
        o0.x += p0.x; o0.y += p0.y; o0.z += p0.z; o0.w += p0.w;
        o1.x += p1.x; o1.y += p1.y; o1.z += p1.z; o1.w += p1.w;
        o2.x += p2.x; o2.y += p2.y; o2.z += p2.z; o2.w += p2.w;
        o3.x += p3.x; o3.y += p3.y; o3.z += p3.z; o3.w += p3.w;
        float* ub = u + (size_t)(b * PTH + s0) * PF + (f4 << 2);
        *reinterpret_cast<float4*>(ub)          = o0;
        *reinterpret_cast<float4*>(ub + PF)     = o1;
        *reinterpret_cast<float4*>(ub + 2 * PF) = o2;
        *reinterpret_cast<float4*>(ub + 3 * PF) = o3;
    }
}

// ---------------------------------------------------------------------------
// kernel_launch
// Inputs: v [16,128,512], h [16,64,512], W [512,256], U [512,256], b [256], w [256,1]
// Output: u [16,64,512] float32
// ---------------------------------------------------------------------------
extern "C" void kernel_launch(void* const* d_in, const int* in_sizes, int n_in,
                              void* d_out, int out_size)
{
    const float* v    = (const float*)d_in[0];
    const float* h    = (const float*)d_in[1];
    const float* W    = (const float*)d_in[2];
    const float* U    = (const float*)d_in[3];
    const float* bvec = (const float*)d_in[4];
    const float* wvec = (const float*)d_in[5];
    float* out = (float*)d_out;

    prep_kernel<<<832, 256>>>(v, h, W, U);
    mma_gemm_kernel<<<192, 256>>>(bvec);
    attn_fused_kernel<<<dim3(PTH / 4, PB), 256>>>(v, wvec, out);
}

// round 14
// speedup vs baseline: 1.4012x; 1.4012x over previous
#include <cuda_runtime.h>
#include <cuda_bf16.h>
#include <cstdint>

// Problem constants
#define PB  16
#define PTV 128
#define PTH 64
#define PF  512
#define PH  512
#define PD  256
#define KDIM 512

#define KITERS 32

// ---------------------------------------------------------------------------
// Device scratch
// ---------------------------------------------------------------------------
__device__ float g_WvT[PB * PD * PTV];   // [b][d][t]
__device__ float g_Uhb[PB * PTH * PD];   // [b][s][d]

__device__ __forceinline__ float tanh_approx(float x) {
    float r; asm("tanh.approx.f32 %0, %1;" : "=f"(r) : "f"(x)); return r;
}
__device__ __forceinline__ uint32_t smem_u32(const void* p) {
    uint32_t a;
    asm("{ .reg .u64 t; cvta.to.shared.u64 t, %1; cvt.u32.u64 %0, t; }" : "=r"(a) : "l"(p));
    return a;
}
__device__ __forceinline__ void cp_async16(uint32_t smem_addr, const void* gptr) {
    asm volatile("cp.async.cg.shared.global [%0], [%1], 16;" :: "r"(smem_addr), "l"(gptr));
}
#define CP_COMMIT() asm volatile("cp.async.commit_group;" ::: "memory")
#define CP_WAIT(N)  asm volatile("cp.async.wait_group %0;" :: "n"(N) : "memory")

// Split-pair: packed bf16-hi of (a,b) [lo half = a]; lop gets residual pair.
__device__ __forceinline__ uint32_t splitpair(float a, float b, uint32_t& lop) {
    uint32_t hp;
    asm("cvt.rn.bf16x2.f32 %0, %1, %2;" : "=r"(hp) : "f"(b), "f"(a));
    float ha = __uint_as_float(hp << 16);
    float hb = __uint_as_float(hp & 0xFFFF0000u);
    float la = a - ha;
    float lb = b - hb;
    asm("cvt.rn.bf16x2.f32 %0, %1, %2;" : "=r"(lop) : "f"(lb), "f"(la));
    return hp;
}

__device__ __forceinline__ void mma_bf16(float* c, uint32_t a0, uint32_t a1, uint32_t a2, uint32_t a3,
                                         uint32_t b0, uint32_t b1) {
    asm volatile(
        "mma.sync.aligned.m16n8k16.row.col.f32.bf16.bf16.f32 "
        "{%0,%1,%2,%3}, {%4,%5,%6,%7}, {%8,%9}, {%0,%1,%2,%3};"
        : "+f"(c[0]), "+f"(c[1]), "+f"(c[2]), "+f"(c[3])
        : "r"(a0), "r"(a1), "r"(a2), "r"(a3), "r"(b0), "r"(b1));
}

// ---------------------------------------------------------------------------
// Fused-convert bf16 split-float MMA GEMM. 192 CTAs x 256 threads (8 warps).
// Raw f32 tiles staged via 4-stage cp.async (A: 64 rows x 16 k, row stride
// 80B padded; B: 16 k x 64 n, row stride 272B padded). Each thread gathers
// its m16n8k16 fragments from smem, splits f32 -> bf16 hi/lo IN-KERNEL
// (hidden under HMMA on the ALU/FMA pipes), and issues
// D = Ahi*Bhi + Ahi*Blo + Alo*Bhi (12 HMMA/warp-kit).
// Epilogue: v-tiles -> g_WvT transposed; h-tiles -> g_Uhb + bias.
// ---------------------------------------------------------------------------
#define A_STRIDE 20          // floats per A row (80B, 16B-aligned, padded)
#define B_STRIDE 68          // floats per B row (272B, 16B-aligned, padded)
#define A_BYTES  (64 * 80)   // 5120
#define B_BYTES  (16 * 272)  // 4352
#define STG      (A_BYTES + B_BYTES)   // 9472 per stage

__global__ __launch_bounds__(256) void mma_gemm_kernel(
    const float* __restrict__ v, const float* __restrict__ h,
    const float* __restrict__ W, const float* __restrict__ U,
    const float* __restrict__ bias)
{
    __shared__ __align__(16) char s_raw[4 * STG];    // 37888 B
    const uint32_t sbase = smem_u32(s_raw);

    const int tile  = blockIdx.x >> 2;     // 0..47
    const int ntile = blockIdx.x & 3;      // 0..3
    const int tid   = threadIdx.x;
    const int lane  = tid & 31;
    const int wid   = tid >> 5;
    const int wm    = wid >> 2;            // 0..1
    const int wn    = wid & 3;             // 0..3
    const bool is_v = tile < 32;

    float acc[2][2][4];
#pragma unroll
    for (int mf = 0; mf < 2; mf++)
#pragma unroll
        for (int nf = 0; nf < 2; nf++)
#pragma unroll
            for (int r = 0; r < 4; r++) acc[mf][nf][r] = 0.0f;

    // Global sources
    const float* Abase = is_v ? v + (size_t)(tile * 64) * KDIM
                              : h + (size_t)(tile - 32) * 64 * KDIM;
    const float* Bbase = (is_v ? W : U) + ntile * 64;

    // cp.async mappings (per stage):
    //  A: thread -> row = tid>>2 (0..63), seg = tid&3;  16B from row slice
    //  B: thread -> row = tid>>4 (0..15), seg = tid&15; 16B from k-row
    const int a_row = tid >> 2, a_seg = tid & 3;
    const int b_row = tid >> 4, b_seg = tid & 15;
    const float* a_src0 = Abase + (size_t)a_row * KDIM + a_seg * 4;
    const float* b_src0 = Bbase + (size_t)b_row * PD + b_seg * 4;
    const uint32_t a_dst = a_row * 80 + a_seg * 16;
    const uint32_t b_dst = A_BYTES + b_row * 272 + b_seg * 16;

#pragma unroll
    for (int s = 0; s < 3; s++) {
        cp_async16(sbase + s * STG + a_dst, a_src0 + s * 16);
        cp_async16(sbase + s * STG + b_dst, b_src0 + (size_t)s * 16 * PD);
        CP_COMMIT();
    }

    const int kl = (lane & 3) * 2;
    const int g  = lane >> 2;

#pragma unroll 4
    for (int kit = 0; kit < KITERS; kit++) {
        const int p = kit & 3;
        CP_WAIT(2);
        __syncthreads();
        if (kit + 3 < KITERS) {
            const int s = (kit + 3) & 3;
            cp_async16(sbase + s * STG + a_dst, a_src0 + (kit + 3) * 16);
            cp_async16(sbase + s * STG + b_dst, b_src0 + (size_t)(kit + 3) * 16 * PD);
        }
        CP_COMMIT();

        const float* As = reinterpret_cast<const float*>(s_raw + p * STG);
        const float* Bs = reinterpret_cast<const float*>(s_raw + p * STG + A_BYTES);

        // Gather + split A fragments
        uint4 Ah[2], Al[2];
#pragma unroll
        for (int mf = 0; mf < 2; mf++) {
            int r0 = wm * 32 + mf * 16 + g;
            float2 x00 = *reinterpret_cast<const float2*>(&As[r0 * A_STRIDE + kl]);
            float2 x10 = *reinterpret_cast<const float2*>(&As[(r0 + 8) * A_STRIDE + kl]);
            float2 x08 = *reinterpret_cast<const float2*>(&As[r0 * A_STRIDE + kl + 8]);
            float2 x18 = *reinterpret_cast<const float2*>(&As[(r0 + 8) * A_STRIDE + kl + 8]);
            Ah[mf].x = splitpair(x00.x, x00.y, Al[mf].x);
            Ah[mf].y = splitpair(x10.x, x10.y, Al[mf].y);
            Ah[mf].z = splitpair(x08.x, x08.y, Al[mf].z);
            Ah[mf].w = splitpair(x18.x, x18.y, Al[mf].w);
        }
        // Gather + split B fragments
        uint4 Bf[2];
#pragma unroll
        for (int nf = 0; nf < 2; nf++) {
            int n = (wn * 2 + nf) * 8 + g;
            float xa = Bs[kl * B_STRIDE + n];
            float xb = Bs[(kl + 1) * B_STRIDE + n];
            float xc = Bs[(kl + 8) * B_STRIDE + n];
            float xd = Bs[(kl + 9) * B_STRIDE + n];
            Bf[nf].x = splitpair(xa, xb, Bf[nf].z);
            Bf[nf].y = splitpair(xc, xd, Bf[nf].w);
        }

#pragma unroll
        for (int mf = 0; mf < 2; mf++) {
#pragma unroll
            for (int nf = 0; nf < 2; nf++) {
                mma_bf16(acc[mf][nf], Ah[mf].x, Ah[mf].y, Ah[mf].z, Ah[mf].w, Bf[nf].x, Bf[nf].y);
                mma_bf16(acc[mf][nf], Ah[mf].x, Ah[mf].y, Ah[mf].z, Ah[mf].w, Bf[nf].z, Bf[nf].w);
                mma_bf16(acc[mf][nf], Al[mf].x, Al[mf].y, Al[mf].z, Al[mf].w, Bf[nf].x, Bf[nf].y);
            }
        }
    }
    __syncthreads();

    // Epilogue. C frag rows g/g+8, cols tc/tc+1.
    const int tc = (lane & 3) * 2;

    if (is_v) {
        float (*st)[72] = reinterpret_cast<float (*)[72]>(s_raw);   // 18KB < 37888
#pragma unroll
        for (int mf = 0; mf < 2; mf++) {
#pragma unroll
            for (int nf = 0; nf < 2; nf++) {
                int ml = wm * 32 + mf * 16 + g;
                int nl = wn * 16 + nf * 8 + tc;
                st[nl][ml]         = acc[mf][nf][0];
                st[nl + 1][ml]     = acc[mf][nf][1];
                st[nl][ml + 8]     = acc[mf][nf][2];
                st[nl + 1][ml + 8] = acc[mf][nf][3];
            }
        }
        __syncthreads();
        const int b  = tile >> 1;
        const int t0 = (tile & 1) * 64;
        const int d0 = ntile * 64;
        for (int i = tid; i < 64 * 16; i += 256) {
            int d  = i >> 4;
            int m4 = (i & 15) << 2;
            float4 val = *reinterpret_cast<const float4*>(&st[d][m4]);
            *reinterpret_cast<float4*>(
                g_WvT + ((size_t)(b * PD + d0 + d) << 7) + t0 + m4) = val;
        }
    } else {
#pragma unroll
        for (int mf = 0; mf < 2; mf++) {
            int row = (tile - 32) * 64 + wm * 32 + mf * 16 + g;
#pragma unroll
            for (int nf = 0; nf < 2; nf++) {
                int col = ntile * 64 + wn * 16 + nf * 8 + tc;
                float b0 = __ldg(bias + col);
                float b1 = __ldg(bias + col + 1);
                float2 o0 = make_float2(acc[mf][nf][0] + b0, acc[mf][nf][1] + b1);
                float2 o1 = make_float2(acc[mf][nf][2] + b0, acc[mf][nf][3] + b1);
                *reinterpret_cast<float2*>(g_Uhb + (size_t)row * PD + col)       = o0;
                *reinterpret_cast<float2*>(g_Uhb + (size_t)(row + 8) * PD + col) = o1;
            }
        }
    }
}

// ---------------------------------------------------------------------------
// Fused scores + softmax + context. Grid (16,16) = 256 CTAs, 256 threads.
// Round-11 structure; phase A uses float4 broadcast loads of su/sw and
// f32 tanh (1 MUFU/elem).
// ---------------------------------------------------------------------------
__global__ __launch_bounds__(256) void attn_fused_kernel(
    const float* __restrict__ v, const float* __restrict__ wvec,
    float* __restrict__ u)
{
    const int b = blockIdx.y;
    const int s0 = blockIdx.x * 4;
    const int tid = threadIdx.x;
    const int t = tid & 127;
    const int dh = tid >> 7;

    __shared__ float su[4][PD];
    __shared__ float sw[PD];
    __shared__ float rmax[4][4];
    __shared__ float rsum[4][4];
    __shared__ float sbeta[4][PTV];
    __shared__ float spA[4][PTV];
    __shared__ __align__(16) char sraw[32768];

    const uint32_t sb_addr = smem_u32(sraw);

    if (tid < PD) sw[tid] = wvec[tid];
    for (int i = tid; i < 4 * PD; i += 256)
        su[i >> 8][i & 255] = g_Uhb[((size_t)(b * PTH + s0 + (i >> 8)) << 8) + (i & 255)];

    // ---- Phase A ----
    const float4* wsrc = reinterpret_cast<const float4*>(g_WvT + ((size_t)b << 15));
#pragma unroll
    for (int j = 0; j < 4; j++)
        cp_async16(sb_addr + (j * 256 + tid) * 16, wsrc + j * 256 + tid);
    CP_COMMIT();

    float a0 = 0.f, a1 = 0.f, a2 = 0.f, a3 = 0.f;
    for (int c = 0; c < 8; c++) {
        const int p = c & 1;
        CP_WAIT(0);
        __syncthreads();
        if (c + 1 < 8) {
            const float4* src = wsrc + (size_t)(c + 1) * 1024;
            uint32_t dst = sb_addr + (p ^ 1) * 16384;
#pragma unroll
            for (int j = 0; j < 4; j++)
                cp_async16(dst + (j * 256 + tid) * 16, src + j * 256 + tid);
        }
        CP_COMMIT();

        const float* wb = reinterpret_cast<const float*>(sraw + p * 16384); // [32][128]
        const int rbase = dh * 16;
        const int dbase = c * 32 + rbase;
#pragma unroll
        for (int j = 0; j < 16; j += 4) {
            float wv0 = wb[(rbase + j + 0) * 128 + t];
            float wv1 = wb[(rbase + j + 1) * 128 + t];
            float wv2 = wb[(rbase + j + 2) * 128 + t];
            float wv3 = wb[(rbase + j + 3) * 128 + t];
            float4 w4  = *reinterpret_cast<const float4*>(&sw[dbase + j]);
            float4 s0v = *reinterpret_cast<const float4*>(&su[0][dbase + j]);
            float4 s1v = *reinterpret_cast<const float4*>(&su[1][dbase + j]);
            float4 s2v = *reinterpret_cast<const float4*>(&su[2][dbase + j]);
            float4 s3v = *reinterpret_cast<const float4*>(&su[3][dbase + j]);

            a0 = fmaf(w4.x, tanh_approx(s0v.x + wv0), a0);
            a1 = fmaf(w4.x, tanh_approx(s1v.x + wv0), a1);
            a2 = fmaf(w4.x, tanh_approx(s2v.x + wv0), a2);
            a3 = fmaf(w4.x, tanh_approx(s3v.x + wv0), a3);

            a0 = fmaf(w4.y, tanh_approx(s0v.y + wv1), a0);
            a1 = fmaf(w4.y, tanh_approx(s1v.y + wv1), a1);
            a2 = fmaf(w4.y, tanh_approx(s2v.y + wv1), a2);
            a3 = fmaf(w4.y, tanh_approx(s3v.y + wv1), a3);

            a0 = fmaf(w4.z, tanh_approx(s0v.z + wv2), a0);
            a1 = fmaf(w4.z, tanh_approx(s1v.z + wv2), a1);
            a2 = fmaf(w4.z, tanh_approx(s2v.z + wv2), a2);
            a3 = fmaf(w4.z, tanh_approx(s3v.z + wv2), a3);

            a0 = fmaf(w4.w, tanh_approx(s0v.w + wv3), a0);
            a1 = fmaf(w4.w, tanh_approx(s1v.w + wv3), a1);
            a2 = fmaf(w4.w, tanh_approx(s2v.w + wv3), a2);
            a3 = fmaf(w4.w, tanh_approx(s3v.w + wv3), a3);
        }
    }
    __syncthreads();

    // combine d-halves
    if (dh == 1) {
        spA[0][t] = a0; spA[1][t] = a1; spA[2][t] = a2; spA[3][t] = a3;
    }
    __syncthreads();

    float e0, e1, e2, e3;
    const int lane = t & 31;
    const int wq = t >> 5;
    if (dh == 0) {
        a0 += spA[0][t]; a1 += spA[1][t]; a2 += spA[2][t]; a3 += spA[3][t];
        float m0 = a0, m1 = a1, m2 = a2, m3 = a3;
#pragma unroll
        for (int off = 16; off; off >>= 1) {
            m0 = fmaxf(m0, __shfl_xor_sync(0xffffffffu, m0, off));
            m1 = fmaxf(m1, __shfl_xor_sync(0xffffffffu, m1, off));
            m2 = fmaxf(m2, __shfl_xor_sync(0xffffffffu, m2, off));
            m3 = fmaxf(m3, __shfl_xor_sync(0xffffffffu, m3, off));
        }
        if (lane == 0) { rmax[0][wq] = m0; rmax[1][wq] = m1; rmax[2][wq] = m2; rmax[3][wq] = m3; }
    }
    __syncthreads();
    if (dh == 0) {
        float m0 = fmaxf(fmaxf(rmax[0][0], rmax[0][1]), fmaxf(rmax[0][2], rmax[0][3]));
        float m1 = fmaxf(fmaxf(rmax[1][0], rmax[1][1]), fmaxf(rmax[1][2], rmax[1][3]));
        float m2 = fmaxf(fmaxf(rmax[2][0], rmax[2][1]), fmaxf(rmax[2][2], rmax[2][3]));
        float m3 = fmaxf(fmaxf(rmax[3][0], rmax[3][1]), fmaxf(rmax[3][2], rmax[3][3]));
        e0 = __expf(a0 - m0); e1 = __expf(a1 - m1);
        e2 = __expf(a2 - m2); e3 = __expf(a3 - m3);
        float s0v = e0, s1v = e1, s2v = e2, s3v = e3;
#pragma unroll
        for (int off = 16; off; off >>= 1) {
            s0v += __shfl_xor_sync(0xffffffffu, s0v, off);
            s1v += __shfl_xor_sync(0xffffffffu, s1v, off);
            s2v += __shfl_xor_sync(0xffffffffu, s2v, off);
            s3v += __shfl_xor_sync(0xffffffffu, s3v, off);
        }
        if (lane == 0) { rsum[0][wq] = s0v; rsum[1][wq] = s1v; rsum[2][wq] = s2v; rsum[3][wq] = s3v; }
    }
    __syncthreads();
    if (dh == 0) {
        float i0 = 1.0f / ((rsum[0][0] + rsum[0][1]) + (rsum[0][2] + rsum[0][3]));
        float i1 = 1.0f / ((rsum[1][0] + rsum[1][1]) + (rsum[1][2] + rsum[1][3]));
        float i2 = 1.0f / ((rsum[2][0] + rsum[2][1]) + (rsum[2][2] + rsum[2][3]));
        float i3 = 1.0f / ((rsum[3][0] + rsum[3][1]) + (rsum[3][2] + rsum[3][3]));
        sbeta[0][t] = e0 * i0;
        sbeta[1][t] = e1 * i1;
        sbeta[2][t] = e2 * i2;
        sbeta[3][t] = e3 * i3;
    }
    __syncthreads();

    // ---- Phase B: context ----
    const int f4 = t;
    const int th = dh;

    const float4* vsrc = reinterpret_cast<const float4*>(v + (size_t)b * PTV * PF);
#pragma unroll
    for (int j = 0; j < 4; j++)
        cp_async16(sb_addr + (j * 256 + tid) * 16, vsrc + j * 256 + tid);
    CP_COMMIT();

    float4 o0 = make_float4(0.f, 0.f, 0.f, 0.f);
    float4 o1 = make_float4(0.f, 0.f, 0.f, 0.f);
    float4 o2 = make_float4(0.f, 0.f, 0.f, 0.f);
    float4 o3 = make_float4(0.f, 0.f, 0.f, 0.f);

    for (int ch = 0; ch < 16; ch++) {
        const int p = ch & 1;
        CP_WAIT(0);
        __syncthreads();
        if (ch + 1 < 16) {
            const float4* src = vsrc + (size_t)(ch + 1) * 1024;
            uint32_t dst = sb_addr + (p ^ 1) * 16384;
#pragma unroll
            for (int j = 0; j < 4; j++)
                cp_async16(dst + (j * 256 + tid) * 16, src + j * 256 + tid);
        }
        CP_COMMIT();

        const float4* vs = reinterpret_cast<const float4*>(sraw + p * 16384); // [8][128]
#pragma unroll
        for (int j = 0; j < 4; j++) {
            int tl = th * 4 + j;
            int tt = ch * 8 + tl;
            float4 vr = vs[tl * 128 + f4];
            float b0 = sbeta[0][tt];
            float b1 = sbeta[1][tt];
            float b2 = sbeta[2][tt];
            float b3 = sbeta[3][tt];
            o0.x += b0 * vr.x; o0.y += b0 * vr.y; o0.z += b0 * vr.z; o0.w += b0 * vr.w;
            o1.x += b1 * vr.x; o1.y += b1 * vr.y; o1.z += b1 * vr.z; o1.w += b1 * vr.w;
            o2.x += b2 * vr.x; o2.y += b2 * vr.y; o2.z += b2 * vr.z; o2.w += b2 * vr.w;
            o3.x += b3 * vr.x; o3.y += b3 * vr.y; o3.z += b3 * vr.z; o3.w += b3 * vr.w;
        }
    }
    __syncthreads();

    float4* spB = reinterpret_cast<float4*>(sraw);
    if (th == 1) {
        spB[0 * 128 + f4] = o0;
        spB[1 * 128 + f4] = o1;
        spB[2 * 128 + f4] = o2;
        spB[3 * 128 + f4] = o3;
    }
    __syncthreads();
    if (th == 0) {
        float4 p0 = spB[0 * 128 + f4];
        float4 p1 = spB[1 * 128 + f4];
        float4 p2 = spB[2 * 128 + f4];
        float4 p3 = spB[3 * 128 + f4];
        o0.x += p0.x; o0.y += p0.y; o0.z += p0.z; o0.w += p0.w;
        o1.x += p1.x; o1.y += p1.y; o1.z += p1.z; o1.w += p1.w;
        o2.x += p2.x; o2.y += p2.y; o2.z += p2.z; o2.w += p2.w;
        o3.x += p3.x; o3.y += p3.y; o3.z += p3.z; o3.w += p3.w;
        float* ub = u + (size_t)(b * PTH + s0) * PF + (f4 << 2);
        *reinterpret_cast<float4*>(ub)          = o0;
        *reinterpret_cast<float4*>(ub + PF)     = o1;
        *reinterpret_cast<float4*>(ub + 2 * PF) = o2;
        *reinterpret_cast<float4*>(ub + 3 * PF) = o3;
    }
}

// ---------------------------------------------------------------------------
// kernel_launch
// Inputs: v [16,128,512], h [16,64,512], W [512,256], U [512,256], b [256], w [256,1]
// Output: u [16,64,512] float32
// ---------------------------------------------------------------------------
extern "C" void kernel_launch(void* const* d_in, const int* in_sizes, int n_in,
                              void* d_out, int out_size)
{
    const float* v    = (const float*)d_in[0];
    const float* h    = (const float*)d_in[1];
    const float* W    = (const float*)d_in[2];
    const float* U    = (const float*)d_in[3];
    const float* bvec = (const float*)d_in[4];
    const float* wvec = (const float*)d_in[5];
    float* out = (float*)d_out;

    mma_gemm_kernel<<<192, 256>>>(v, h, W, U, bvec);
    attn_fused_kernel<<<dim3(PTH / 4, PB), 256>>>(v, wvec, out);
}

// round 16
// speedup vs baseline: 1.4971x; 1.0684x over previous
#include <cuda_runtime.h>
#include <cuda_bf16.h>
#include <cstdint>

// Problem constants
#define PB  16
#define PTV 128
#define PTH 64
#define PF  512
#define PH  512
#define PD  256
#define KDIM 512

#define MTILES 48
#define KITERS 32

// ---------------------------------------------------------------------------
// Device scratch
// ---------------------------------------------------------------------------
__device__ uint4 g_Afrag[MTILES * KITERS * 4 * 2 * 32];
__device__ uint4 g_Bfrag[2 * KITERS * 32 * 32];

__device__ float g_WvT[PB * PD * PTV];   // [b][d][t]
__device__ float g_Uhb[PB * PTH * PD];   // [b][s][d]
__device__ float g_beta[PB * PTH * PTV]; // [b][s][t]

__device__ __forceinline__ float tanh_approx(float x) {
    float r; asm("tanh.approx.f32 %0, %1;" : "=f"(r) : "f"(x)); return r;
}
__device__ __forceinline__ uint32_t smem_u32(const void* p) {
    uint32_t a;
    asm("{ .reg .u64 t; cvta.to.shared.u64 t, %1; cvt.u32.u64 %0, t; }" : "=r"(a) : "l"(p));
    return a;
}
__device__ __forceinline__ void cp_async16(uint32_t smem_addr, const void* gptr) {
    asm volatile("cp.async.cg.shared.global [%0], [%1], 16;" :: "r"(smem_addr), "l"(gptr));
}
#define CP_COMMIT() asm volatile("cp.async.commit_group;" ::: "memory")
#define CP_WAIT(N)  asm volatile("cp.async.wait_group %0;" :: "n"(N) : "memory")

// Split-pair: packed bf16-hi of (a,b) [lo half = a]; lop gets residual pair.
__device__ __forceinline__ uint32_t splitpair(float a, float b, uint32_t& lop) {
    uint32_t hp;
    asm("cvt.rn.bf16x2.f32 %0, %1, %2;" : "=r"(hp) : "f"(b), "f"(a));
    float ha = __uint_as_float(hp << 16);
    float hb = __uint_as_float(hp & 0xFFFF0000u);
    float la = a - ha;
    float lb = b - hb;
    asm("cvt.rn.bf16x2.f32 %0, %1, %2;" : "=r"(lop) : "f"(lb), "f"(la));
    return hp;
}

__device__ __forceinline__ void mma_bf16(float* c, uint32_t a0, uint32_t a1, uint32_t a2, uint32_t a3,
                                         uint32_t b0, uint32_t b1) {
    asm volatile(
        "mma.sync.aligned.m16n8k16.row.col.f32.bf16.bf16.f32 "
        "{%0,%1,%2,%3}, {%4,%5,%6,%7}, {%8,%9}, {%0,%1,%2,%3};"
        : "+f"(c[0]), "+f"(c[1]), "+f"(c[2]), "+f"(c[3])
        : "r"(a0), "r"(a1), "r"(a2), "r"(a3), "r"(b0), "r"(b1));
}

// ---------------------------------------------------------------------------
// Prep kernel (round-11 version: 1024 CTAs, no smem)
// ---------------------------------------------------------------------------
__global__ __launch_bounds__(256) void prep_kernel(
    const float* __restrict__ v, const float* __restrict__ h,
    const float* __restrict__ W, const float* __restrict__ U)
{
    int gid = blockIdx.x * 256 + threadIdx.x;
    if (gid < 196608) {
        int lane = gid & 31;
        int mf   = (gid >> 5) & 3;
        int kit  = (gid >> 7) & 31;
        int tile = gid >> 12;

        int rloc = tile * 64 + mf * 16 + (lane >> 2);
        const float* r0p;
        if (tile < 32) r0p = v + (size_t)rloc * KDIM;
        else           r0p = h + (size_t)(rloc - 2048) * KDIM;
        const float* r1p = r0p + 8 * KDIM;
        int k0 = kit * 16 + (lane & 3) * 2;

        float2 x00 = *reinterpret_cast<const float2*>(r0p + k0);
        float2 x10 = *reinterpret_cast<const float2*>(r1p + k0);
        float2 x08 = *reinterpret_cast<const float2*>(r0p + k0 + 8);
        float2 x18 = *reinterpret_cast<const float2*>(r1p + k0 + 8);

        uint4 vh, vl;
        vh.x = splitpair(x00.x, x00.y, vl.x);
        vh.y = splitpair(x10.x, x10.y, vl.y);
        vh.z = splitpair(x08.x, x08.y, vl.z);
        vh.w = splitpair(x18.x, x18.y, vl.w);

        size_t base = ((((size_t)tile * KITERS + kit) * 4 + mf) * 2) * 32 + lane;
        g_Afrag[base]      = vh;
        g_Afrag[base + 32] = vl;
    } else if (gid < 262144) {
        int item = gid - 196608;
        int lane = item & 31;
        int nf   = (item >> 5) & 31;
        int kit  = (item >> 10) & 31;
        int mat  = item >> 15;

        const float* Bsrc = mat ? U : W;
        int n = nf * 8 + (lane >> 2);
        int k0 = kit * 16 + (lane & 3) * 2;

        float xa = Bsrc[(size_t)(k0 + 0) * PD + n];
        float xb = Bsrc[(size_t)(k0 + 1) * PD + n];
        float xc = Bsrc[(size_t)(k0 + 8) * PD + n];
        float xd = Bsrc[(size_t)(k0 + 9) * PD + n];

        uint4 out;
        out.x = splitpair(xa, xb, out.z);
        out.y = splitpair(xc, xd, out.w);
        g_Bfrag[(((size_t)mat * KITERS + kit) * 32 + nf) * 32 + lane] = out;
    }
}

// ---------------------------------------------------------------------------
// bf16 split-float MMA GEMM (round-11 version)
// ---------------------------------------------------------------------------
__global__ __launch_bounds__(256) void mma_gemm_kernel(const float* __restrict__ bias)
{
    __shared__ __align__(16) char s_raw[32768];
    uint4* sbuf = reinterpret_cast<uint4*>(s_raw);
    const uint32_t sbase = smem_u32(s_raw);

    const int tile  = blockIdx.x >> 2;
    const int ntile = blockIdx.x & 3;
    const int tid   = threadIdx.x;
    const int lane  = tid & 31;
    const int wid   = tid >> 5;
    const int wm    = wid >> 2;
    const int wn    = wid & 3;
    const bool is_v = tile < 32;

    float acc[2][2][4];
#pragma unroll
    for (int mf = 0; mf < 2; mf++)
#pragma unroll
        for (int nf = 0; nf < 2; nf++)
#pragma unroll
            for (int r = 0; r < 4; r++) acc[mf][nf][r] = 0.0f;

    const uint4* Asrc = g_Afrag + (size_t)tile * (KITERS * 256);
    const uint4* Bsrc = g_Bfrag + ((size_t)(is_v ? 0 : 1) * KITERS * 32 + ntile * 8) * 32;

#pragma unroll
    for (int s = 0; s < 3; s++) {
        cp_async16(sbase + (s * 512 + tid) * 16,       Asrc + (size_t)s * 256 + tid);
        cp_async16(sbase + (s * 512 + 256 + tid) * 16, Bsrc + (size_t)s * 1024 + tid);
        CP_COMMIT();
    }

    const int aoff0 = ((wm * 2 + 0) * 2) * 32 + lane;
    const int boff0 = 256 + (wn * 2) * 32 + lane;

#pragma unroll 4
    for (int kit = 0; kit < KITERS; kit++) {
        const int p = kit & 3;
        CP_WAIT(2);
        __syncthreads();
        if (kit + 3 < KITERS) {
            const int s = (kit + 3) & 3;
            cp_async16(sbase + (s * 512 + tid) * 16,       Asrc + (size_t)(kit + 3) * 256 + tid);
            cp_async16(sbase + (s * 512 + 256 + tid) * 16, Bsrc + (size_t)(kit + 3) * 1024 + tid);
        }
        CP_COMMIT();

        const uint4* buf = sbuf + p * 512;
        uint4 Ah[2], Al[2], Bf[2];
        Ah[0] = buf[aoff0];
        Al[0] = buf[aoff0 + 32];
        Ah[1] = buf[aoff0 + 64];
        Al[1] = buf[aoff0 + 96];
        Bf[0] = buf[boff0];
        Bf[1] = buf[boff0 + 32];
#pragma unroll
        for (int mf = 0; mf < 2; mf++) {
#pragma unroll
            for (int nf = 0; nf < 2; nf++) {
                mma_bf16(acc[mf][nf], Ah[mf].x, Ah[mf].y, Ah[mf].z, Ah[mf].w, Bf[nf].x, Bf[nf].y);
                mma_bf16(acc[mf][nf], Ah[mf].x, Ah[mf].y, Ah[mf].z, Ah[mf].w, Bf[nf].z, Bf[nf].w);
                mma_bf16(acc[mf][nf], Al[mf].x, Al[mf].y, Al[mf].z, Al[mf].w, Bf[nf].x, Bf[nf].y);
            }
        }
    }
    __syncthreads();

    const int g  = lane >> 2;
    const int tc = (lane & 3) * 2;

    if (is_v) {
        float (*st)[72] = reinterpret_cast<float (*)[72]>(s_raw);
#pragma unroll
        for (int mf = 0; mf < 2; mf++) {
#pragma unroll
            for (int nf = 0; nf < 2; nf++) {
                int ml = wm * 32 + mf * 16 + g;
                int nl = wn * 16 + nf * 8 + tc;
                st[nl][ml]         = acc[mf][nf][0];
                st[nl + 1][ml]     = acc[mf][nf][1];
                st[nl][ml + 8]     = acc[mf][nf][2];
                st[nl + 1][ml + 8] = acc[mf][nf][3];
            }
        }
        __syncthreads();
        const int b  = tile >> 1;
        const int t0 = (tile & 1) * 64;
        const int d0 = ntile * 64;
        for (int i = tid; i < 64 * 16; i += 256) {
            int d  = i >> 4;
            int m4 = (i & 15) << 2;
            float4 val = *reinterpret_cast<const float4*>(&st[d][m4]);
            *reinterpret_cast<float4*>(
                g_WvT + ((size_t)(b * PD + d0 + d) << 7) + t0 + m4) = val;
        }
    } else {
#pragma unroll
        for (int mf = 0; mf < 2; mf++) {
            int row = (tile - 32) * 64 + wm * 32 + mf * 16 + g;
#pragma unroll
            for (int nf = 0; nf < 2; nf++) {
                int col = ntile * 64 + wn * 16 + nf * 8 + tc;
                float b0 = __ldg(bias + col);
                float b1 = __ldg(bias + col + 1);
                float2 o0 = make_float2(acc[mf][nf][0] + b0, acc[mf][nf][1] + b1);
                float2 o1 = make_float2(acc[mf][nf][2] + b0, acc[mf][nf][3] + b1);
                *reinterpret_cast<float2*>(g_Uhb + (size_t)row * PD + col)       = o0;
                *reinterpret_cast<float2*>(g_Uhb + (size_t)(row + 8) * PD + col) = o1;
            }
        }
    }
}

// ---------------------------------------------------------------------------
// Scores + softmax -> g_beta. Grid (16,16) = 256 CTAs, 256 threads.
// Phase A identical to round 11/14 (f32 tanh, float4 broadcast su/sw loads,
// WvT streamed via 2-stage cp.async). No context phase.
// ---------------------------------------------------------------------------
__global__ __launch_bounds__(256) void scores_kernel(
    const float* __restrict__ wvec, float* __restrict__ beta)
{
    const int b = blockIdx.y;
    const int s0 = blockIdx.x * 4;
    const int tid = threadIdx.x;
    const int t = tid & 127;
    const int dh = tid >> 7;

    __shared__ float su[4][PD];
    __shared__ float sw[PD];
    __shared__ float rmax[4][4];
    __shared__ float rsum[4][4];
    __shared__ float spA[4][PTV];
    __shared__ __align__(16) char sraw[32768];

    const uint32_t sb_addr = smem_u32(sraw);

    if (tid < PD) sw[tid] = wvec[tid];
    for (int i = tid; i < 4 * PD; i += 256)
        su[i >> 8][i & 255] = g_Uhb[((size_t)(b * PTH + s0 + (i >> 8)) << 8) + (i & 255)];

    const float4* wsrc = reinterpret_cast<const float4*>(g_WvT + ((size_t)b << 15));
#pragma unroll
    for (int j = 0; j < 4; j++)
        cp_async16(sb_addr + (j * 256 + tid) * 16, wsrc + j * 256 + tid);
    CP_COMMIT();

    float a0 = 0.f, a1 = 0.f, a2 = 0.f, a3 = 0.f;
    for (int c = 0; c < 8; c++) {
        const int p = c & 1;
        CP_WAIT(0);
        __syncthreads();
        if (c + 1 < 8) {
            const float4* src = wsrc + (size_t)(c + 1) * 1024;
            uint32_t dst = sb_addr + (p ^ 1) * 16384;
#pragma unroll
            for (int j = 0; j < 4; j++)
                cp_async16(dst + (j * 256 + tid) * 16, src + j * 256 + tid);
        }
        CP_COMMIT();

        const float* wb = reinterpret_cast<const float*>(sraw + p * 16384); // [32][128]
        const int rbase = dh * 16;
        const int dbase = c * 32 + rbase;
#pragma unroll
        for (int j = 0; j < 16; j += 4) {
            float wv0 = wb[(rbase + j + 0) * 128 + t];
            float wv1 = wb[(rbase + j + 1) * 128 + t];
            float wv2 = wb[(rbase + j + 2) * 128 + t];
            float wv3 = wb[(rbase + j + 3) * 128 + t];
            float4 w4  = *reinterpret_cast<const float4*>(&sw[dbase + j]);
            float4 s0v = *reinterpret_cast<const float4*>(&su[0][dbase + j]);
            float4 s1v = *reinterpret_cast<const float4*>(&su[1][dbase + j]);
            float4 s2v = *reinterpret_cast<const float4*>(&su[2][dbase + j]);
            float4 s3v = *reinterpret_cast<const float4*>(&su[3][dbase + j]);

            a0 = fmaf(w4.x, tanh_approx(s0v.x + wv0), a0);
            a1 = fmaf(w4.x, tanh_approx(s1v.x + wv0), a1);
            a2 = fmaf(w4.x, tanh_approx(s2v.x + wv0), a2);
            a3 = fmaf(w4.x, tanh_approx(s3v.x + wv0), a3);

            a0 = fmaf(w4.y, tanh_approx(s0v.y + wv1), a0);
            a1 = fmaf(w4.y, tanh_approx(s1v.y + wv1), a1);
            a2 = fmaf(w4.y, tanh_approx(s2v.y + wv1), a2);
            a3 = fmaf(w4.y, tanh_approx(s3v.y + wv1), a3);

            a0 = fmaf(w4.z, tanh_approx(s0v.z + wv2), a0);
            a1 = fmaf(w4.z, tanh_approx(s1v.z + wv2), a1);
            a2 = fmaf(w4.z, tanh_approx(s2v.z + wv2), a2);
            a3 = fmaf(w4.z, tanh_approx(s3v.z + wv2), a3);

            a0 = fmaf(w4.w, tanh_approx(s0v.w + wv3), a0);
            a1 = fmaf(w4.w, tanh_approx(s1v.w + wv3), a1);
            a2 = fmaf(w4.w, tanh_approx(s2v.w + wv3), a2);
            a3 = fmaf(w4.w, tanh_approx(s3v.w + wv3), a3);
        }
    }
    __syncthreads();

    // combine d-halves
    if (dh == 1) {
        spA[0][t] = a0; spA[1][t] = a1; spA[2][t] = a2; spA[3][t] = a3;
    }
    __syncthreads();

    float e0, e1, e2, e3;
    const int lane = t & 31;
    const int wq = t >> 5;
    if (dh == 0) {
        a0 += spA[0][t]; a1 += spA[1][t]; a2 += spA[2][t]; a3 += spA[3][t];
        float m0 = a0, m1 = a1, m2 = a2, m3 = a3;
#pragma unroll
        for (int off = 16; off; off >>= 1) {
            m0 = fmaxf(m0, __shfl_xor_sync(0xffffffffu, m0, off));
            m1 = fmaxf(m1, __shfl_xor_sync(0xffffffffu, m1, off));
            m2 = fmaxf(m2, __shfl_xor_sync(0xffffffffu, m2, off));
            m3 = fmaxf(m3, __shfl_xor_sync(0xffffffffu, m3, off));
        }
        if (lane == 0) { rmax[0][wq] = m0; rmax[1][wq] = m1; rmax[2][wq] = m2; rmax[3][wq] = m3; }
    }
    __syncthreads();
    if (dh == 0) {
        float m0 = fmaxf(fmaxf(rmax[0][0], rmax[0][1]), fmaxf(rmax[0][2], rmax[0][3]));
        float m1 = fmaxf(fmaxf(rmax[1][0], rmax[1][1]), fmaxf(rmax[1][2], rmax[1][3]));
        float m2 = fmaxf(fmaxf(rmax[2][0], rmax[2][1]), fmaxf(rmax[2][2], rmax[2][3]));
        float m3 = fmaxf(fmaxf(rmax[3][0], rmax[3][1]), fmaxf(rmax[3][2], rmax[3][3]));
        e0 = __expf(a0 - m0); e1 = __expf(a1 - m1);
        e2 = __expf(a2 - m2); e3 = __expf(a3 - m3);
        float s0v = e0, s1v = e1, s2v = e2, s3v = e3;
#pragma unroll
        for (int off = 16; off; off >>= 1) {
            s0v += __shfl_xor_sync(0xffffffffu, s0v, off);
            s1v += __shfl_xor_sync(0xffffffffu, s1v, off);
            s2v += __shfl_xor_sync(0xffffffffu, s2v, off);
            s3v += __shfl_xor_sync(0xffffffffu, s3v, off);
        }
        if (lane == 0) { rsum[0][wq] = s0v; rsum[1][wq] = s1v; rsum[2][wq] = s2v; rsum[3][wq] = s3v; }
    }
    __syncthreads();
    if (dh == 0) {
        float i0 = 1.0f / ((rsum[0][0] + rsum[0][1]) + (rsum[0][2] + rsum[0][3]));
        float i1 = 1.0f / ((rsum[1][0] + rsum[1][1]) + (rsum[1][2] + rsum[1][3]));
        float i2 = 1.0f / ((rsum[2][0] + rsum[2][1]) + (rsum[2][2] + rsum[2][3]));
        float i3 = 1.0f / ((rsum[3][0] + rsum[3][1]) + (rsum[3][2] + rsum[3][3]));
        float* bout = beta + ((size_t)(b * PTH + s0) << 7) + t;
        bout[0]       = e0 * i0;
        bout[128]     = e1 * i1;
        bout[256]     = e2 * i2;
        bout[384]     = e3 * i3;
    }
}

// ---------------------------------------------------------------------------
// Context: u[b][s][f] = sum_t beta[b][s][t] * v[b][t][f]
// Grid (4 f-chunks, 4 s-groups, 16 b) = 256 CTAs, 256 threads.
// v f-slice (128t x 128f = 64KB) streamed via 2-stage cp.async, 8KB chunks;
// each v element read by exactly 4 CTAs chip-wide (16 MB total, was 64 MB).
// Thread = (f4 = tid&31, sr = tid>>5 -> s pair 2sr, 2sr+1).
// ---------------------------------------------------------------------------
__global__ __launch_bounds__(256) void context_kernel(
    const float* __restrict__ v, const float* __restrict__ beta,
    float* __restrict__ u)
{
    const int b  = blockIdx.z;
    const int s0 = blockIdx.y * 16;
    const int f0 = blockIdx.x * 128;
    const int tid = threadIdx.x;
    const int f4 = tid & 31;
    const int sr = tid >> 5;          // 0..7
    const int sA = sr << 1;
    const int sB = sA + 1;

    __shared__ float sb[16][PTV];                     // 8 KB beta tile
    __shared__ __align__(16) char sraw[2][8192];      // v staging

    const uint32_t sb_addr = smem_u32(sraw);

    // beta tile (contiguous 8KB)
    {
        const float4* src = reinterpret_cast<const float4*>(beta + ((size_t)(b * PTH + s0) << 7));
        float4* dst = reinterpret_cast<float4*>(&sb[0][0]);
        dst[tid]       = src[tid];
        dst[tid + 256] = src[tid + 256];
    }

    // v chunk mapping: chunk ch covers rows t = ch*16 .. +16, cols f0..f0+128.
    // Thread transfers idx = tid, tid+256 of 512 float4: r = idx>>5, c = idx&31.
    const float* vbase = v + (size_t)b * PTV * PF + f0;
    {
        const int r0 = tid >> 5, c0 = tid & 31;
        const int r1 = (tid + 256) >> 5, c1 = tid & 31;
        cp_async16(sb_addr + tid * 16,         vbase + (size_t)r0 * PF + c0 * 4);
        cp_async16(sb_addr + (tid + 256) * 16, vbase + (size_t)r1 * PF + c1 * 4);
    }
    CP_COMMIT();

    float4 a0 = make_float4(0.f, 0.f, 0.f, 0.f);
    float4 a1 = make_float4(0.f, 0.f, 0.f, 0.f);

    for (int ch = 0; ch < 8; ch++) {
        const int p = ch & 1;
        CP_WAIT(0);
        __syncthreads();             // chunk ch resident (+ sb published at ch=0)
        if (ch + 1 < 8) {
            const float* src = vbase + (size_t)(ch + 1) * 16 * PF;
            uint32_t dst = sb_addr + (p ^ 1) * 8192;
            const int r0 = tid >> 5, r1 = (tid + 256) >> 5, c = tid & 31;
            cp_async16(dst + tid * 16,         src + (size_t)r0 * PF + c * 4);
            cp_async16(dst + (tid + 256) * 16, src + (size_t)r1 * PF + c * 4);
        }
        CP_COMMIT();

        const float4* vs = reinterpret_cast<const float4*>(sraw[p]);   // [16][32]
#pragma unroll
        for (int r = 0; r < 16; r++) {
            float4 vr = vs[r * 32 + f4];
            int tt = ch * 16 + r;
            float b0 = sb[sA][tt];
            float b1 = sb[sB][tt];
            a0.x += b0 * vr.x; a0.y += b0 * vr.y; a0.z += b0 * vr.z; a0.w += b0 * vr.w;
            a1.x += b1 * vr.x; a1.y += b1 * vr.y; a1.z += b1 * vr.z; a1.w += b1 * vr.w;
        }
    }

    float* ub = u + (size_t)(b * PTH + s0 + sA) * PF + f0 + (f4 << 2);
    *reinterpret_cast<float4*>(ub)      = a0;
    *reinterpret_cast<float4*>(ub + PF) = a1;
}

// ---------------------------------------------------------------------------
// kernel_launch
// Inputs: v [16,128,512], h [16,64,512], W [512,256], U [512,256], b [256], w [256,1]
// Output: u [16,64,512] float32
// ---------------------------------------------------------------------------
extern "C" void kernel_launch(void* const* d_in, const int* in_sizes, int n_in,
                              void* d_out, int out_size)
{
    const float* v    = (const float*)d_in[0];
    const float* h    = (const float*)d_in[1];
    const float* W    = (const float*)d_in[2];
    const float* U    = (const float*)d_in[3];
    const float* bvec = (const float*)d_in[4];
    const float* wvec = (const float*)d_in[5];
    float* out = (float*)d_out;

    float* beta_ptr; cudaGetSymbolAddress((void**)&beta_ptr, g_beta);

    prep_kernel<<<1024, 256>>>(v, h, W, U);
    mma_gemm_kernel<<<192, 256>>>(bvec);
    scores_kernel<<<dim3(PTH / 4, PB), 256>>>(wvec, beta_ptr);
    context_kernel<<<dim3(PF / 128, PTH / 16, PB), 256>>>(v, beta_ptr, out);
}